// round 17
// baseline (speedup 1.0000x reference)
#include <cuda_runtime.h>

#define L       4096
#define NCDIM   64
#define NCELLS  (NCDIM * NCDIM * NCDIM)

#define SBLK    1024              // scan kernel blocks
#define STHR    256               // scan kernel threads
#define F4TOT   ((L * L) / 4)     // 4,194,304 float4s
#define F4PB    (F4TOT / SBLK)    // 4096 float4 per block
#define CTHR    256

__device__ double g_clash = 0.0;
__device__ double g_pairn = 0.0;   // sum (d-9)^2 over contacts with |i-j|>=3
__device__ double g_cnt   = 0.0;   // sum of ALL contact entries (n_pairs)
__device__ int    d_head[NCELLS];  // 0 = empty, else point_index + 1
__device__ int    d_next[L];

__device__ __forceinline__ float fsqrt_approx(float x) {
    float r;
    asm("sqrt.approx.f32 %0, %1;" : "=f"(r) : "f"(x));
    return r;
}

__device__ __forceinline__ float warp_sum(float v) {
    v += __shfl_down_sync(0xffffffffu, v, 16);
    v += __shfl_down_sync(0xffffffffu, v, 8);
    v += __shfl_down_sync(0xffffffffu, v, 4);
    v += __shfl_down_sync(0xffffffffu, v, 2);
    v += __shfl_down_sync(0xffffffffu, v, 1);
    return v;
}

__device__ __forceinline__ int cell_coord(float x) {
    int c = (int)floorf(x * 0.25f) + 32;       // cell size 4.0 > 3.4
    return min(max(c, 0), NCDIM - 1);
}

// ---- kernel 1: stream cmap; count contacts; pair term on sparse hits ------
__global__ void __launch_bounds__(STHR)
scan_kernel(const float* __restrict__ coords,
            const float* __restrict__ cmap)
{
    __shared__ float red[16];
    const int tid = threadIdx.x;
    const size_t base = (size_t)blockIdx.x * F4PB;
    const float4* cm4 = (const float4*)cmap;

    float cnt = 0.0f, ap = 0.0f;

#pragma unroll
    for (int h = 0; h < 4; ++h) {
        // stage 4 coalesced LDG.128 (MLP)
        float4 v[4];
        int    ix[4];
#pragma unroll
        for (int m = 0; m < 4; ++m) {
            ix[m] = (int)(base + (size_t)(h * 4 + m) * STHR + tid);
            v[m]  = __ldg(cm4 + ix[m]);
        }
#pragma unroll
        for (int m = 0; m < 4; ++m) {
            const float4 vv = v[m];
            float s4 = (vv.x + vv.y) + (vv.z + vv.w);   // exact: entries in {0,1}
            cnt += s4;
            if (s4 > 0.0f) {                             // ~4% of float4s
                const int idx = ix[m];
                const int i   = idx >> 10;               // 1024 f4 per row
                const int j   = (idx & 1023) * 4;
                const float xi = __ldg(coords + 3 * i + 0);
                const float yi = __ldg(coords + 3 * i + 1);
                const float zi = __ldg(coords + 3 * i + 2);
                const float cv[4] = {vv.x, vv.y, vv.z, vv.w};
#pragma unroll
                for (int e = 0; e < 4; ++e) {
                    if (cv[e] > 0.5f) {
                        const int jj = j + e;
                        int sep = jj - i; if (sep < 0) sep = -sep;
                        if (sep >= 3) {
                            float dx = __ldg(coords + 3 * jj + 0) - xi;
                            float dy = __ldg(coords + 3 * jj + 1) - yi;
                            float dz = __ldg(coords + 3 * jj + 2) - zi;
                            float d  = fsqrt_approx(fmaf(dz, dz, fmaf(dy, dy, dx * dx))) + 1e-8f;
                            float u  = d - 9.0f;          // target = 6.0 * 1.5
                            ap = fmaf(u, u, ap);
                        }
                    }
                }
            }
        }
    }

    cnt = warp_sum(cnt);
    ap  = warp_sum(ap);
    const int wid = tid >> 5, lane = tid & 31;
    if (lane == 0) { red[wid] = cnt; red[8 + wid] = ap; }
    __syncthreads();
    if (tid == 0) {
        float cs = 0.0f, ps = 0.0f;
        for (int w = 0; w < 8; ++w) { cs += red[w]; ps += red[8 + w]; }
        atomicAdd(&g_cnt,   (double)cs);
        atomicAdd(&g_pairn, (double)ps);
    }
}

// ---- kernel 2: build cell linked lists ------------------------------------
__global__ void __launch_bounds__(CTHR)
build_kernel(const float* __restrict__ coords)
{
    const int i = blockIdx.x * CTHR + threadIdx.x;
    if (i < L) {
        const int cx = cell_coord(__ldg(coords + 3 * i + 0));
        const int cy = cell_coord(__ldg(coords + 3 * i + 1));
        const int cz = cell_coord(__ldg(coords + 3 * i + 2));
        const int cell = (cx << 12) | (cy << 6) | cz;
        d_next[i] = atomicExch(&d_head[cell], i + 1);
    }
}

// ---- kernel 3: clash energy via neighbor cells ----------------------------
__global__ void __launch_bounds__(CTHR)
clash_kernel(const float* __restrict__ coords)
{
    __shared__ float red[8];
    const int tid = threadIdx.x;
    const int t   = blockIdx.x * CTHR + tid;

    float acl = 0.0f;
    if (t < 3 * L) {
        const int i  = t / 3;
        const int zo = t % 3 - 1;
        const float xi = __ldg(coords + 3 * i + 0);
        const float yi = __ldg(coords + 3 * i + 1);
        const float zi = __ldg(coords + 3 * i + 2);
        const int cx = cell_coord(xi);
        const int cy = cell_coord(yi);
        const int cz = cell_coord(zi);
        const int czn = cz + zo;
        if (czn >= 0 && czn < NCDIM) {
            for (int yo = -1; yo <= 1; ++yo) {
                const int cyn = cy + yo;
                if (cyn < 0 || cyn >= NCDIM) continue;
                for (int xo = -1; xo <= 1; ++xo) {
                    const int cxn = cx + xo;
                    if (cxn < 0 || cxn >= NCDIM) continue;
                    int h = d_head[(cxn << 12) | (cyn << 6) | czn];
                    int guard = 0;
                    while (h && guard < L) {
                        ++guard;                          // hard cap: cannot fire on valid data
                        const int jj = h - 1;
                        h = d_next[jj];
                        if (jj <= i - 3) {               // each unordered pair once
                            float dx = __ldg(coords + 3 * jj + 0) - xi;
                            float dy = __ldg(coords + 3 * jj + 1) - yi;
                            float dz = __ldg(coords + 3 * jj + 2) - zi;
                            float d2 = fmaf(dz, dz, fmaf(dy, dy, dx * dx));
                            float tt = fmaxf(3.4f - (fsqrt_approx(d2) + 1e-8f), 0.0f);
                            acl = fmaf(tt, tt, acl);
                        }
                    }
                }
            }
        }
    }

    acl = warp_sum(acl);
    const int wid = tid >> 5, lane = tid & 31;
    if (lane == 0) red[wid] = acl;
    __syncthreads();
    if (tid == 0) {
        float cs = 0.0f;
        for (int w = 0; w < 8; ++w) cs += red[w];
        if (cs != 0.0f) atomicAdd(&g_clash, (double)cs);
    }
}

// ---- kernel 4: bond + combine + reset for next graph replay ---------------
__global__ void __launch_bounds__(CTHR)
finalize_kernel(const float* __restrict__ coords, float* __restrict__ out)
{
    __shared__ float red[8];
    const int tid = threadIdx.x;

    float b = 0.0f;
    for (int k = tid; k < L - 1; k += CTHR) {
        float dx = __ldg(coords + 3 * k + 3) - __ldg(coords + 3 * k + 0);
        float dy = __ldg(coords + 3 * k + 4) - __ldg(coords + 3 * k + 1);
        float dz = __ldg(coords + 3 * k + 5) - __ldg(coords + 3 * k + 2);
        float d  = fsqrt_approx(fmaf(dz, dz, fmaf(dy, dy, dx * dx)));
        float t  = d - 6.0f;                 // IDEAL_C1_C1
        b = fmaf(t, t, b);
    }
    b = warp_sum(b);
    const int wid = tid >> 5, lane = tid & 31;
    if (lane == 0) red[wid] = b;
    __syncthreads();
    if (tid == 0) {
        float bs = 0.0f;
        for (int w = 0; w < 8; ++w) bs += red[w];
        double e_bond  = (double)bs / (double)(L - 1);
        double e_clash = g_clash / (double)L;    // unordered j>=i+3, counted once
        double cnt     = g_cnt < 1.0 ? 1.0 : g_cnt;
        double e_pair  = g_pairn / cnt;
        out[0] = (float)(e_bond + 2.0 * e_clash + 0.5 * e_pair);
        g_clash = 0.0;
        g_pairn = 0.0;
        g_cnt   = 0.0;
    }
    __syncthreads();
    // reset cell heads for the next replay (d_next needs no reset)
    for (int c = tid; c < NCELLS; c += CTHR)
        d_head[c] = 0;
}

extern "C" void kernel_launch(void* const* d_in, const int* in_sizes, int n_in,
                              void* d_out, int out_size) {
    const float* a0 = (const float*)d_in[0];
    const float* a1 = (const float*)d_in[1];
    // coords is the small input (L*3), contact_map the big one (L*L)
    const float* coords = (in_sizes[0] < in_sizes[1]) ? a0 : a1;
    const float* cmap   = (in_sizes[0] < in_sizes[1]) ? a1 : a0;

    scan_kernel    <<<SBLK, STHR>>>(coords, cmap);
    build_kernel   <<<(L + CTHR - 1) / CTHR, CTHR>>>(coords);
    clash_kernel   <<<(3 * L + CTHR - 1) / CTHR, CTHR>>>(coords);
    finalize_kernel<<<1, CTHR>>>(coords, (float*)d_out);
}